// round 5
// baseline (speedup 1.0000x reference)
#include <cuda_runtime.h>
#include <cuda_bf16.h>
#include <cstddef>

// Problem constants
#define Bc  4
#define Sc  2048
#define Dc  1024
#define Hc  16
#define DKc 64
#define BHc (Bc*Hc)                     // 64
#define SCALEc 0.125f                   // DK^-0.5
#define EPSc 1e-6f

constexpr size_t XE = (size_t)Bc*Sc*Dc;       // 8,388,608  (x / per-head tensors)
constexpr size_t AE = (size_t)Bc*Hc*Sc*Sc;    // 268,435,456 (attn)

// ---------------- scratch (device globals: allocation-free) ----------------
__device__ float g_qh[XE];        // [B,H,S,DK]
__device__ float g_kh[XE];
__device__ float g_vh[XE];
__device__ float g_ao[XE];        // attn@V re-assembled [B,S,H*DK]
__device__ float g_x[XE];         // pre-LN activations
__device__ float g_attn_fb[AE];   // fallback if harness only wants x

// ============================================================================
// GEMM: C[M,N] = A[M,K] @ Bm[K,N] + bias (+ resid), 128x128x8 tiles, 8x8/thread
// headLayout=1 writes C into [B,H,S,DK] layout (proj); 0 = row-major (FC).
// M implied by gridDim.y*128.
// ============================================================================
__global__ __launch_bounds__(256) void sgemm128(
    const float* __restrict__ A, const float* __restrict__ Bm,
    const float* __restrict__ bias, const float* __restrict__ resid,
    float* __restrict__ C, int K, int N, int headLayout)
{
    __shared__ float As[8][128];
    __shared__ float Bs[8][128];
    const int t  = threadIdx.x;
    const int tx = t & 15, ty = t >> 4;
    const int arow = t >> 1, acol = (t & 1) * 4;
    const int brow = t >> 5, bcol = (t & 31) * 4;
    const int mBase = blockIdx.y * 128;
    const int nBase = blockIdx.x * 128;

    const float* Ap = A  + (size_t)(mBase + arow) * K + acol;
    const float* Bp = Bm + (size_t)brow * N + nBase + bcol;

    float acc[8][8];
    #pragma unroll
    for (int i = 0; i < 8; i++)
        #pragma unroll
        for (int j = 0; j < 8; j++) acc[i][j] = 0.f;

    for (int k0 = 0; k0 < K; k0 += 8) {
        float4 av = *(const float4*)Ap;
        float4 bv = *(const float4*)Bp;
        As[acol+0][arow] = av.x; As[acol+1][arow] = av.y;
        As[acol+2][arow] = av.z; As[acol+3][arow] = av.w;
        *(float4*)&Bs[brow][bcol] = bv;
        __syncthreads();
        #pragma unroll
        for (int kk = 0; kk < 8; kk++) {
            float ra[8], rb[8];
            *(float4*)(ra)   = *(const float4*)&As[kk][ty*8];
            *(float4*)(ra+4) = *(const float4*)&As[kk][ty*8+4];
            *(float4*)(rb)   = *(const float4*)&Bs[kk][tx*8];
            *(float4*)(rb+4) = *(const float4*)&Bs[kk][tx*8+4];
            #pragma unroll
            for (int i = 0; i < 8; i++)
                #pragma unroll
                for (int j = 0; j < 8; j++)
                    acc[i][j] += ra[i] * rb[j];
        }
        __syncthreads();
        Ap += 8;
        Bp += (size_t)8 * N;
    }

    #pragma unroll
    for (int i = 0; i < 8; i++) {
        const int row = mBase + ty*8 + i;
        #pragma unroll
        for (int j = 0; j < 8; j++) {
            const int col = nBase + tx*8 + j;
            float v = acc[i][j] + bias[col];
            if (resid) v += resid[(size_t)row * N + col];
            if (headLayout) {
                const int b  = row >> 11;    // row / S (S=2048)
                const int s  = row & 2047;
                const int h  = col >> 6;     // col / 64
                const int dk = col & 63;
                C[(((size_t)(b*Hc + h)) * Sc + s) * DKc + dk] = v;
            } else {
                C[(size_t)row * N + col] = v;
            }
        }
    }
}

// ============================================================================
// Scores: per (b,h) C[2048,2048] = qh[2048,64] @ kh[2048,64]^T * scale
// ============================================================================
__global__ __launch_bounds__(256) void scores_k(
    const float* __restrict__ qh, const float* __restrict__ kh,
    float* __restrict__ attn_out)
{
    float* attn = attn_out ? attn_out : g_attn_fb;
    __shared__ float As[8][128];
    __shared__ float Bs[8][128];
    const int t  = threadIdx.x;
    const int tx = t & 15, ty = t >> 4;
    const int lrow = t >> 1, lcol = (t & 1) * 4;
    const int bh = blockIdx.z;

    const float* Ap = qh + (size_t)bh * Sc * DKc
                         + (size_t)(blockIdx.y*128 + lrow) * DKc + lcol;
    const float* Bp = kh + (size_t)bh * Sc * DKc
                         + (size_t)(blockIdx.x*128 + lrow) * DKc + lcol;
    float* Cp = attn + (size_t)bh * Sc * Sc;

    float acc[8][8];
    #pragma unroll
    for (int i = 0; i < 8; i++)
        #pragma unroll
        for (int j = 0; j < 8; j++) acc[i][j] = 0.f;

    #pragma unroll
    for (int k0 = 0; k0 < DKc; k0 += 8) {
        float4 av = *(const float4*)Ap;  Ap += 8;
        float4 bv = *(const float4*)Bp;  Bp += 8;
        As[lcol+0][lrow] = av.x; As[lcol+1][lrow] = av.y;
        As[lcol+2][lrow] = av.z; As[lcol+3][lrow] = av.w;
        Bs[lcol+0][lrow] = bv.x; Bs[lcol+1][lrow] = bv.y;
        Bs[lcol+2][lrow] = bv.z; Bs[lcol+3][lrow] = bv.w;
        __syncthreads();
        #pragma unroll
        for (int kk = 0; kk < 8; kk++) {
            float ra[8], rb[8];
            *(float4*)(ra)   = *(const float4*)&As[kk][ty*8];
            *(float4*)(ra+4) = *(const float4*)&As[kk][ty*8+4];
            *(float4*)(rb)   = *(const float4*)&Bs[kk][tx*8];
            *(float4*)(rb+4) = *(const float4*)&Bs[kk][tx*8+4];
            #pragma unroll
            for (int i = 0; i < 8; i++)
                #pragma unroll
                for (int j = 0; j < 8; j++)
                    acc[i][j] += ra[i] * rb[j];
        }
        __syncthreads();
    }

    #pragma unroll
    for (int i = 0; i < 8; i++) {
        const size_t row = (size_t)(blockIdx.y*128 + ty*8 + i);
        #pragma unroll
        for (int j = 0; j < 8; j++) {
            const int col = blockIdx.x*128 + tx*8 + j;
            Cp[row * Sc + col] = acc[i][j] * SCALEc;
        }
    }
}

// ============================================================================
// Row softmax over S=2048 (in place). One CTA (256 thr) per row, 8 elems/thr.
// ============================================================================
__global__ __launch_bounds__(256) void softmax_k(float* __restrict__ attn_out)
{
    float* attn = attn_out ? attn_out : g_attn_fb;
    __shared__ float red[256];
    const int t = threadIdx.x;
    float* p = attn + (size_t)blockIdx.x * Sc;

    float v[8];
    float m = -1e30f;
    #pragma unroll
    for (int i = 0; i < 8; i++) { v[i] = p[t + i*256]; m = fmaxf(m, v[i]); }
    red[t] = m; __syncthreads();
    for (int s = 128; s > 0; s >>= 1) {
        if (t < s) red[t] = fmaxf(red[t], red[t+s]);
        __syncthreads();
    }
    m = red[0]; __syncthreads();

    float sum = 0.f;
    #pragma unroll
    for (int i = 0; i < 8; i++) { v[i] = expf(v[i] - m); sum += v[i]; }
    red[t] = sum; __syncthreads();
    for (int s = 128; s > 0; s >>= 1) {
        if (t < s) red[t] += red[t+s];
        __syncthreads();
    }
    const float inv = 1.f / red[0];
    #pragma unroll
    for (int i = 0; i < 8; i++) p[t + i*256] = v[i] * inv;
}

// ============================================================================
// attn @ V per (b,h): [2048,2048] @ [2048,64]. 128x64x16 tiles, 8x4/thread.
// Writes re-assembled [B,S,H*DK].
// ============================================================================
__global__ __launch_bounds__(256) void av_k(
    const float* __restrict__ attn_out, const float* __restrict__ vh,
    float* __restrict__ ao)
{
    const float* attn = attn_out ? attn_out : g_attn_fb;
    __shared__ float As[16][128];
    __shared__ float Bs[16][64];
    const int t  = threadIdx.x;
    const int tx = t & 15, ty = t >> 4;     // 4 cols x 8 rows per thread
    const int bh = blockIdx.y;
    const int mBase = blockIdx.x * 128;
    const int arow = t >> 1, acol = (t & 1) * 8;
    const int brow = t >> 4, bcol = (t & 15) * 4;

    const float* Ap = attn + (size_t)bh * Sc * Sc + (size_t)(mBase + arow) * Sc + acol;
    const float* Bp = vh   + (size_t)bh * Sc * DKc + (size_t)brow * DKc + bcol;

    float acc[8][4];
    #pragma unroll
    for (int i = 0; i < 8; i++)
        #pragma unroll
        for (int j = 0; j < 4; j++) acc[i][j] = 0.f;

    for (int k0 = 0; k0 < Sc; k0 += 16) {
        float4 a0 = *(const float4*)(Ap);
        float4 a1 = *(const float4*)(Ap + 4);
        float4 bv = *(const float4*)(Bp);
        As[acol+0][arow] = a0.x; As[acol+1][arow] = a0.y;
        As[acol+2][arow] = a0.z; As[acol+3][arow] = a0.w;
        As[acol+4][arow] = a1.x; As[acol+5][arow] = a1.y;
        As[acol+6][arow] = a1.z; As[acol+7][arow] = a1.w;
        *(float4*)&Bs[brow][bcol] = bv;
        __syncthreads();
        #pragma unroll
        for (int kk = 0; kk < 16; kk++) {
            float ra[8], rb[4];
            *(float4*)(ra)   = *(const float4*)&As[kk][ty*8];
            *(float4*)(ra+4) = *(const float4*)&As[kk][ty*8+4];
            *(float4*)(rb)   = *(const float4*)&Bs[kk][tx*4];
            #pragma unroll
            for (int i = 0; i < 8; i++)
                #pragma unroll
                for (int j = 0; j < 4; j++)
                    acc[i][j] += ra[i] * rb[j];
        }
        __syncthreads();
        Ap += 16;
        Bp += (size_t)16 * DKc;
    }

    const int b = bh >> 4, h = bh & 15;
    #pragma unroll
    for (int i = 0; i < 8; i++) {
        const int srow = mBase + ty*8 + i;
        #pragma unroll
        for (int j = 0; j < 4; j++) {
            const int dk = tx*4 + j;
            ao[((size_t)(b*Sc + srow)) * Dc + h*DKc + dk] = acc[i][j];
        }
    }
}

// ============================================================================
// LayerNorm over D=1024. One CTA per row, 4 elems/thread.
// ============================================================================
__global__ __launch_bounds__(256) void ln_k(
    const float* __restrict__ x, const float* __restrict__ gamma,
    const float* __restrict__ beta, float* __restrict__ out)
{
    __shared__ float r1[256];
    __shared__ float r2[256];
    const int t = threadIdx.x;
    const float* p = x + (size_t)blockIdx.x * Dc;

    float v[4];
    float s = 0.f, sq = 0.f;
    #pragma unroll
    for (int i = 0; i < 4; i++) {
        v[i] = p[t + i*256];
        s += v[i]; sq += v[i]*v[i];
    }
    r1[t] = s; r2[t] = sq; __syncthreads();
    for (int w = 128; w > 0; w >>= 1) {
        if (t < w) { r1[t] += r1[t+w]; r2[t] += r2[t+w]; }
        __syncthreads();
    }
    const float mu  = r1[0] * (1.f/Dc);
    const float var = r2[0] * (1.f/Dc) - mu*mu;
    const float inv = rsqrtf(var + EPSc);
    float* o = out + (size_t)blockIdx.x * Dc;
    #pragma unroll
    for (int i = 0; i < 4; i++) {
        const int c = t + i*256;
        o[c] = (v[i] - mu) * inv * gamma[c] + beta[c];
    }
}

// ============================================================================
// Launch
// ============================================================================
extern "C" void kernel_launch(void* const* d_in, const int* in_sizes, int n_in,
                              void* d_out, int out_size)
{
    const float* q     = (const float*)d_in[0];
    const float* k     = (const float*)d_in[1];
    const float* v     = (const float*)d_in[2];
    const float* Wq    = (const float*)d_in[3];
    const float* bq    = (const float*)d_in[4];
    const float* Wfc   = (const float*)d_in[5];
    const float* bfc   = (const float*)d_in[6];
    const float* gamma = (const float*)d_in[7];
    const float* beta  = (const float*)d_in[8];

    float* out = (float*)d_out;
    // Tuple order (x, attn): attn region follows x if the harness wants both.
    float* attn_region = ((size_t)out_size >= XE + AE) ? (out + XE) : nullptr;

    float *qh, *kh, *vh, *ao, *xb;
    cudaGetSymbolAddress((void**)&qh, g_qh);
    cudaGetSymbolAddress((void**)&kh, g_kh);
    cudaGetSymbolAddress((void**)&vh, g_vh);
    cudaGetSymbolAddress((void**)&ao, g_ao);
    cudaGetSymbolAddress((void**)&xb, g_x);

    const dim3 gProj(Dc/128, (Bc*Sc)/128);     // (8, 64)
    sgemm128<<<gProj, 256>>>(q, Wq, bq, nullptr, qh, Dc, Hc*DKc, 1);
    sgemm128<<<gProj, 256>>>(k, Wq, bq, nullptr, kh, Dc, Hc*DKc, 1);
    sgemm128<<<gProj, 256>>>(v, Wq, bq, nullptr, vh, Dc, Hc*DKc, 1);

    const dim3 gScores(Sc/128, Sc/128, BHc);   // (16, 16, 64)
    scores_k<<<gScores, 256>>>(qh, kh, attn_region);

    softmax_k<<<BHc * Sc, 256>>>(attn_region); // 131072 rows

    const dim3 gAV(Sc/128, BHc);               // (16, 64)
    av_k<<<gAV, 256>>>(attn_region, vh, ao);

    sgemm128<<<gProj, 256>>>(ao, Wfc, bfc, /*resid=*/q, xb, Dc, Dc, 0);

    ln_k<<<Bc*Sc, 256>>>(xb, gamma, beta, out);
}

// round 11
// speedup vs baseline: 1.9910x; 1.9910x over previous
#include <cuda_runtime.h>
#include <cuda_bf16.h>
#include <cstdint>
#include <cstddef>

// Problem constants
#define Bc  4
#define Sc  2048
#define Dc  1024
#define Hc  16
#define DKc 64
#define BHc (Bc*Hc)                     // 64
#define SCALEc 0.125f                   // DK^-0.5
#define EPSc 1e-6f

constexpr size_t XE = (size_t)Bc*Sc*Dc;       // 8,388,608
constexpr size_t AE = (size_t)Bc*Hc*Sc*Sc;    // 268,435,456

// ---------------- scratch (device globals: allocation-free) ----------------
__device__ float g_qh[XE];        // [B,H,S,DK] (q projected, pre-scaled by 1/8)
__device__ float g_kh[XE];
__device__ float g_vh[XE];
__device__ float g_ao[XE];        // attn@V re-assembled [B,S,H*DK]
__device__ float g_x[XE];         // pre-LN activations
__device__ float g_wt_q[Dc*Dc];   // Wq^T  [N,K] K-major
__device__ float g_wt_fc[Dc*Dc];  // Wfc^T [N,K] K-major
__device__ float g_attn_fb[AE];   // fallback if harness only wants x

// ============================================================================
// tf32 mma.sync helpers (plain sm_80+ PTX: works on compute_103 target)
// ============================================================================
__device__ __forceinline__ uint32_t f2tf(float x) {
    uint32_t r;
    asm("cvt.rna.tf32.f32 %0, %1;" : "=r"(r) : "f"(x));
    return r;
}
// D += A(16x8) @ B(8x8);  A row-major frag, B col-major frag, fp32 accum
__device__ __forceinline__ void mma8(float* d, const uint32_t* a, const uint32_t* b) {
    asm volatile(
        "mma.sync.aligned.m16n8k8.row.col.f32.tf32.tf32.f32 "
        "{%0,%1,%2,%3}, {%4,%5,%6,%7}, {%8,%9}, {%0,%1,%2,%3};"
        : "+f"(d[0]), "+f"(d[1]), "+f"(d[2]), "+f"(d[3])
        : "r"(a[0]), "r"(a[1]), "r"(a[2]), "r"(a[3]), "r"(b[0]), "r"(b[1]));
}

// ============================================================================
// Transpose 1024x1024: Wt[n,k] = W[k,n]
// ============================================================================
__global__ __launch_bounds__(256) void transpose1024(
    const float* __restrict__ W, float* __restrict__ Wt)
{
    __shared__ float tile[32][33];
    const int x = blockIdx.x * 32 + threadIdx.x;
    const int y = blockIdx.y * 32 + threadIdx.y;
    #pragma unroll
    for (int j = 0; j < 32; j += 8)
        tile[threadIdx.y + j][threadIdx.x] = W[(size_t)(y + j) * Dc + x];
    __syncthreads();
    const int xo = blockIdx.y * 32 + threadIdx.x;
    const int yo = blockIdx.x * 32 + threadIdx.y;
    #pragma unroll
    for (int j = 0; j < 32; j += 8)
        Wt[(size_t)(yo + j) * Dc + xo] = tile[threadIdx.x][threadIdx.y + j];
}

// ============================================================================
// Dense GEMM (tf32 mma): C[M,1024] = A[M,1024] @ Bt[1024,1024]^T, +bias,
// *outScale, +resid.  Bt is [N,K] K-major. 128x128 CTA, 8 warps (2x4),
// warp tile 64x32, K double-buffered by 16.
// headLayout=1: write [B,H,S,DK]; else row-major.
// ============================================================================
__global__ __launch_bounds__(256) void gemm_mma(
    const float* __restrict__ A, const float* __restrict__ Bt,
    const float* __restrict__ bias, const float* __restrict__ resid,
    float* __restrict__ C, int headLayout, float outScale)
{
    __shared__ uint32_t As[2][128][20];
    __shared__ uint32_t Bs[2][128][20];

    const int tid  = threadIdx.x;
    const int lane = tid & 31;
    const int warp = tid >> 5;
    const int g = lane >> 2, t = lane & 3;
    const int wm = (warp >> 2) * 64;     // warp row offset in CTA tile
    const int wn = (warp & 3) * 32;      // warp col offset
    const int mBase = blockIdx.y * 128;
    const int nBase = blockIdx.x * 128;

    const int lrow = tid >> 1;
    const int lseg = (tid & 1) * 8;
    const float* Ap = A  + (size_t)(mBase + lrow) * Dc + lseg;
    const float* Bp = Bt + (size_t)(nBase + lrow) * Dc + lseg;

    float acc[4][4][4];
    #pragma unroll
    for (int i = 0; i < 4; i++)
        #pragma unroll
        for (int j = 0; j < 4; j++)
            #pragma unroll
            for (int r = 0; r < 4; r++) acc[i][j][r] = 0.f;

    float4 pa0, pa1, pb0, pb1;
    // prologue: stage kt=0
    pa0 = *(const float4*)(Ap);     pa1 = *(const float4*)(Ap + 4);
    pb0 = *(const float4*)(Bp);     pb1 = *(const float4*)(Bp + 4);
    *(uint4*)&As[0][lrow][lseg]     = make_uint4(f2tf(pa0.x), f2tf(pa0.y), f2tf(pa0.z), f2tf(pa0.w));
    *(uint4*)&As[0][lrow][lseg + 4] = make_uint4(f2tf(pa1.x), f2tf(pa1.y), f2tf(pa1.z), f2tf(pa1.w));
    *(uint4*)&Bs[0][lrow][lseg]     = make_uint4(f2tf(pb0.x), f2tf(pb0.y), f2tf(pb0.z), f2tf(pb0.w));
    *(uint4*)&Bs[0][lrow][lseg + 4] = make_uint4(f2tf(pb1.x), f2tf(pb1.y), f2tf(pb1.z), f2tf(pb1.w));
    __syncthreads();

    #pragma unroll 1
    for (int kt = 0; kt < 64; kt++) {
        const int cur = kt & 1;
        if (kt < 63) {
            const float* ap = Ap + (kt + 1) * 16;
            const float* bp = Bp + (kt + 1) * 16;
            pa0 = *(const float4*)(ap);  pa1 = *(const float4*)(ap + 4);
            pb0 = *(const float4*)(bp);  pb1 = *(const float4*)(bp + 4);
        }
        #pragma unroll
        for (int ks = 0; ks < 2; ks++) {
            const int k0 = ks * 8;
            uint32_t afr[4][4], bfr[4][2];
            #pragma unroll
            for (int mt = 0; mt < 4; mt++) {
                const int r = wm + mt * 16 + g;
                afr[mt][0] = As[cur][r    ][k0 + t];
                afr[mt][1] = As[cur][r + 8][k0 + t];
                afr[mt][2] = As[cur][r    ][k0 + t + 4];
                afr[mt][3] = As[cur][r + 8][k0 + t + 4];
            }
            #pragma unroll
            for (int nt = 0; nt < 4; nt++) {
                const int c = wn + nt * 8 + g;
                bfr[nt][0] = Bs[cur][c][k0 + t];
                bfr[nt][1] = Bs[cur][c][k0 + t + 4];
            }
            #pragma unroll
            for (int mt = 0; mt < 4; mt++)
                #pragma unroll
                for (int nt = 0; nt < 4; nt++)
                    mma8(acc[mt][nt], afr[mt], bfr[nt]);
        }
        __syncthreads();
        if (kt < 63) {
            const int nxt = (kt + 1) & 1;
            *(uint4*)&As[nxt][lrow][lseg]     = make_uint4(f2tf(pa0.x), f2tf(pa0.y), f2tf(pa0.z), f2tf(pa0.w));
            *(uint4*)&As[nxt][lrow][lseg + 4] = make_uint4(f2tf(pa1.x), f2tf(pa1.y), f2tf(pa1.z), f2tf(pa1.w));
            *(uint4*)&Bs[nxt][lrow][lseg]     = make_uint4(f2tf(pb0.x), f2tf(pb0.y), f2tf(pb0.z), f2tf(pb0.w));
            *(uint4*)&Bs[nxt][lrow][lseg + 4] = make_uint4(f2tf(pb1.x), f2tf(pb1.y), f2tf(pb1.z), f2tf(pb1.w));
            __syncthreads();
        }
    }

    // epilogue
    #pragma unroll
    for (int mt = 0; mt < 4; mt++) {
        #pragma unroll
        for (int nt = 0; nt < 4; nt++) {
            const int col = nBase + wn + nt * 8 + t * 2;
            #pragma unroll
            for (int h2 = 0; h2 < 2; h2++) {
                const int row = mBase + wm + mt * 16 + g + h2 * 8;
                float2 v;
                v.x = (acc[mt][nt][h2 * 2 + 0] + bias[col    ]) * outScale;
                v.y = (acc[mt][nt][h2 * 2 + 1] + bias[col + 1]) * outScale;
                if (resid) {
                    const float2 r = *(const float2*)(resid + (size_t)row * Dc + col);
                    v.x += r.x; v.y += r.y;
                }
                if (headLayout) {
                    const int b = row >> 11, sI = row & 2047;
                    const int h = col >> 6, dk = col & 63;
                    *(float2*)(C + (((size_t)(b * Hc + h)) * Sc + sI) * DKc + dk) = v;
                } else {
                    *(float2*)(C + (size_t)row * Dc + col) = v;
                }
            }
        }
    }
}

// ============================================================================
// Scores (tf32 mma): per (b,h) attn[2048,2048] = qh[2048,64] @ kh[2048,64]^T
// (scale pre-folded into qh). Same skeleton, K=64 (4 tiles).
// ============================================================================
__global__ __launch_bounds__(256) void scores_mma(
    const float* __restrict__ qh, const float* __restrict__ kh,
    float* __restrict__ attn_out)
{
    float* attn = attn_out ? attn_out : g_attn_fb;
    __shared__ uint32_t As[2][128][20];
    __shared__ uint32_t Bs[2][128][20];

    const int tid  = threadIdx.x;
    const int lane = tid & 31;
    const int warp = tid >> 5;
    const int g = lane >> 2, t = lane & 3;
    const int wm = (warp >> 2) * 64;
    const int wn = (warp & 3) * 32;
    const int bh = blockIdx.z;
    const int mBase = blockIdx.y * 128;
    const int nBase = blockIdx.x * 128;

    const int lrow = tid >> 1;
    const int lseg = (tid & 1) * 8;
    const float* Ap = qh + (size_t)bh * Sc * DKc + (size_t)(mBase + lrow) * DKc + lseg;
    const float* Bp = kh + (size_t)bh * Sc * DKc + (size_t)(nBase + lrow) * DKc + lseg;
    float* Cp = attn + (size_t)bh * Sc * Sc;

    float acc[4][4][4];
    #pragma unroll
    for (int i = 0; i < 4; i++)
        #pragma unroll
        for (int j = 0; j < 4; j++)
            #pragma unroll
            for (int r = 0; r < 4; r++) acc[i][j][r] = 0.f;

    float4 pa0, pa1, pb0, pb1;
    pa0 = *(const float4*)(Ap);     pa1 = *(const float4*)(Ap + 4);
    pb0 = *(const float4*)(Bp);     pb1 = *(const float4*)(Bp + 4);
    *(uint4*)&As[0][lrow][lseg]     = make_uint4(f2tf(pa0.x), f2tf(pa0.y), f2tf(pa0.z), f2tf(pa0.w));
    *(uint4*)&As[0][lrow][lseg + 4] = make_uint4(f2tf(pa1.x), f2tf(pa1.y), f2tf(pa1.z), f2tf(pa1.w));
    *(uint4*)&Bs[0][lrow][lseg]     = make_uint4(f2tf(pb0.x), f2tf(pb0.y), f2tf(pb0.z), f2tf(pb0.w));
    *(uint4*)&Bs[0][lrow][lseg + 4] = make_uint4(f2tf(pb1.x), f2tf(pb1.y), f2tf(pb1.z), f2tf(pb1.w));
    __syncthreads();

    #pragma unroll
    for (int kt = 0; kt < 4; kt++) {
        const int cur = kt & 1;
        if (kt < 3) {
            const float* ap = Ap + (kt + 1) * 16;
            const float* bp = Bp + (kt + 1) * 16;
            pa0 = *(const float4*)(ap);  pa1 = *(const float4*)(ap + 4);
            pb0 = *(const float4*)(bp);  pb1 = *(const float4*)(bp + 4);
        }
        #pragma unroll
        for (int ks = 0; ks < 2; ks++) {
            const int k0 = ks * 8;
            uint32_t afr[4][4], bfr[4][2];
            #pragma unroll
            for (int mt = 0; mt < 4; mt++) {
                const int r = wm + mt * 16 + g;
                afr[mt][0] = As[cur][r    ][k0 + t];
                afr[mt][1] = As[cur][r + 8][k0 + t];
                afr[mt][2] = As[cur][r    ][k0 + t + 4];
                afr[mt][3] = As[cur][r + 8][k0 + t + 4];
            }
            #pragma unroll
            for (int nt = 0; nt < 4; nt++) {
                const int c = wn + nt * 8 + g;
                bfr[nt][0] = Bs[cur][c][k0 + t];
                bfr[nt][1] = Bs[cur][c][k0 + t + 4];
            }
            #pragma unroll
            for (int mt = 0; mt < 4; mt++)
                #pragma unroll
                for (int nt = 0; nt < 4; nt++)
                    mma8(acc[mt][nt], afr[mt], bfr[nt]);
        }
        __syncthreads();
        if (kt < 3) {
            const int nxt = (kt + 1) & 1;
            *(uint4*)&As[nxt][lrow][lseg]     = make_uint4(f2tf(pa0.x), f2tf(pa0.y), f2tf(pa0.z), f2tf(pa0.w));
            *(uint4*)&As[nxt][lrow][lseg + 4] = make_uint4(f2tf(pa1.x), f2tf(pa1.y), f2tf(pa1.z), f2tf(pa1.w));
            *(uint4*)&Bs[nxt][lrow][lseg]     = make_uint4(f2tf(pb0.x), f2tf(pb0.y), f2tf(pb0.z), f2tf(pb0.w));
            *(uint4*)&Bs[nxt][lrow][lseg + 4] = make_uint4(f2tf(pb1.x), f2tf(pb1.y), f2tf(pb1.z), f2tf(pb1.w));
            __syncthreads();
        }
    }

    #pragma unroll
    for (int mt = 0; mt < 4; mt++) {
        #pragma unroll
        for (int nt = 0; nt < 4; nt++) {
            const int col = nBase + wn + nt * 8 + t * 2;
            #pragma unroll
            for (int h2 = 0; h2 < 2; h2++) {
                const int row = mBase + wm + mt * 16 + g + h2 * 8;
                float2 v = { acc[mt][nt][h2 * 2 + 0], acc[mt][nt][h2 * 2 + 1] };
                *(float2*)(Cp + (size_t)row * Sc + col) = v;
            }
        }
    }
}

// ============================================================================
// Row softmax over S=2048 (in place).
// ============================================================================
__global__ __launch_bounds__(256) void softmax_k(float* __restrict__ attn_out)
{
    float* attn = attn_out ? attn_out : g_attn_fb;
    __shared__ float red[256];
    const int t = threadIdx.x;
    float* p = attn + (size_t)blockIdx.x * Sc;

    float v[8];
    float m = -1e30f;
    #pragma unroll
    for (int i = 0; i < 8; i++) { v[i] = p[t + i*256]; m = fmaxf(m, v[i]); }
    red[t] = m; __syncthreads();
    for (int s = 128; s > 0; s >>= 1) {
        if (t < s) red[t] = fmaxf(red[t], red[t+s]);
        __syncthreads();
    }
    m = red[0]; __syncthreads();

    float sum = 0.f;
    #pragma unroll
    for (int i = 0; i < 8; i++) { v[i] = expf(v[i] - m); sum += v[i]; }
    red[t] = sum; __syncthreads();
    for (int s = 128; s > 0; s >>= 1) {
        if (t < s) red[t] += red[t+s];
        __syncthreads();
    }
    const float inv = 1.f / red[0];
    #pragma unroll
    for (int i = 0; i < 8; i++) p[t + i*256] = v[i] * inv;
}

// ============================================================================
// attn @ V (tf32 mma): per (b,h) [2048,2048] @ [2048,64]. 128x64 CTA,
// 8 warps (4x2), warp tile 32x32, K double-buffered by 16 (128 iters).
// ============================================================================
__global__ __launch_bounds__(256) void av_mma(
    const float* __restrict__ attn_out, const float* __restrict__ vh,
    float* __restrict__ ao)
{
    const float* attn = attn_out ? attn_out : g_attn_fb;
    __shared__ uint32_t As[2][128][20];
    __shared__ uint32_t Bs[2][16][72];

    const int tid  = threadIdx.x;
    const int lane = tid & 31;
    const int warp = tid >> 5;
    const int g = lane >> 2, t = lane & 3;
    const int wm = (warp >> 1) * 32;     // 4 warp rows
    const int wn = (warp & 1) * 32;      // 2 warp cols
    const int bh = blockIdx.y;
    const int mBase = blockIdx.x * 128;

    const int lrow = tid >> 1;
    const int lseg = (tid & 1) * 8;
    const int brow = tid >> 4;           // 0..15
    const int bcol = (tid & 15) * 4;     // 0..60
    const float* Ap = attn + (size_t)bh * Sc * Sc + (size_t)(mBase + lrow) * Sc + lseg;
    const float* Bp = vh   + (size_t)bh * Sc * DKc + (size_t)brow * DKc + bcol;

    float acc[2][4][4];
    #pragma unroll
    for (int i = 0; i < 2; i++)
        #pragma unroll
        for (int j = 0; j < 4; j++)
            #pragma unroll
            for (int r = 0; r < 4; r++) acc[i][j][r] = 0.f;

    float4 pa0, pa1, pb;
    pa0 = *(const float4*)(Ap);  pa1 = *(const float4*)(Ap + 4);
    pb  = *(const float4*)(Bp);
    *(uint4*)&As[0][lrow][lseg]     = make_uint4(f2tf(pa0.x), f2tf(pa0.y), f2tf(pa0.z), f2tf(pa0.w));
    *(uint4*)&As[0][lrow][lseg + 4] = make_uint4(f2tf(pa1.x), f2tf(pa1.y), f2tf(pa1.z), f2tf(pa1.w));
    *(uint4*)&Bs[0][brow][bcol]     = make_uint4(f2tf(pb.x),  f2tf(pb.y),  f2tf(pb.z),  f2tf(pb.w));
    __syncthreads();

    #pragma unroll 1
    for (int kt = 0; kt < 128; kt++) {
        const int cur = kt & 1;
        if (kt < 127) {
            const float* ap = Ap + (kt + 1) * 16;
            const float* bp = Bp + (size_t)(kt + 1) * 16 * DKc;
            pa0 = *(const float4*)(ap);  pa1 = *(const float4*)(ap + 4);
            pb  = *(const float4*)(bp);
        }
        #pragma unroll
        for (int ks = 0; ks < 2; ks++) {
            const int k0 = ks * 8;
            uint32_t afr[2][4], bfr[4][2];
            #pragma unroll
            for (int mt = 0; mt < 2; mt++) {
                const int r = wm + mt * 16 + g;
                afr[mt][0] = As[cur][r    ][k0 + t];
                afr[mt][1] = As[cur][r + 8][k0 + t];
                afr[mt][2] = As[cur][r    ][k0 + t + 4];
                afr[mt][3] = As[cur][r + 8][k0 + t + 4];
            }
            #pragma unroll
            for (int nt = 0; nt < 4; nt++) {
                const int c = wn + nt * 8 + g;
                bfr[nt][0] = Bs[cur][k0 + t    ][c];
                bfr[nt][1] = Bs[cur][k0 + t + 4][c];
            }
            #pragma unroll
            for (int mt = 0; mt < 2; mt++)
                #pragma unroll
                for (int nt = 0; nt < 4; nt++)
                    mma8(acc[mt][nt], afr[mt], bfr[nt]);
        }
        __syncthreads();
        if (kt < 127) {
            const int nxt = (kt + 1) & 1;
            *(uint4*)&As[nxt][lrow][lseg]     = make_uint4(f2tf(pa0.x), f2tf(pa0.y), f2tf(pa0.z), f2tf(pa0.w));
            *(uint4*)&As[nxt][lrow][lseg + 4] = make_uint4(f2tf(pa1.x), f2tf(pa1.y), f2tf(pa1.z), f2tf(pa1.w));
            *(uint4*)&Bs[nxt][brow][bcol]     = make_uint4(f2tf(pb.x),  f2tf(pb.y),  f2tf(pb.z),  f2tf(pb.w));
            __syncthreads();
        }
    }

    const int b = bh >> 4, h = bh & 15;
    #pragma unroll
    for (int mt = 0; mt < 2; mt++) {
        #pragma unroll
        for (int nt = 0; nt < 4; nt++) {
            const int col = wn + nt * 8 + t * 2;     // 0..63 within head
            #pragma unroll
            for (int h2 = 0; h2 < 2; h2++) {
                const int row = mBase + wm + mt * 16 + g + h2 * 8;
                float2 v = { acc[mt][nt][h2 * 2 + 0], acc[mt][nt][h2 * 2 + 1] };
                *(float2*)(ao + ((size_t)(b * Sc + row)) * Dc + h * DKc + col) = v;
            }
        }
    }
}

// ============================================================================
// LayerNorm over D=1024.
// ============================================================================
__global__ __launch_bounds__(256) void ln_k(
    const float* __restrict__ x, const float* __restrict__ gamma,
    const float* __restrict__ beta, float* __restrict__ out)
{
    __shared__ float r1[256];
    __shared__ float r2[256];
    const int t = threadIdx.x;
    const float* p = x + (size_t)blockIdx.x * Dc;

    float v[4];
    float s = 0.f, sq = 0.f;
    #pragma unroll
    for (int i = 0; i < 4; i++) {
        v[i] = p[t + i*256];
        s += v[i]; sq += v[i]*v[i];
    }
    r1[t] = s; r2[t] = sq; __syncthreads();
    for (int w = 128; w > 0; w >>= 1) {
        if (t < w) { r1[t] += r1[t+w]; r2[t] += r2[t+w]; }
        __syncthreads();
    }
    const float mu  = r1[0] * (1.f/Dc);
    const float var = r2[0] * (1.f/Dc) - mu*mu;
    const float inv = rsqrtf(var + EPSc);
    float* o = out + (size_t)blockIdx.x * Dc;
    #pragma unroll
    for (int i = 0; i < 4; i++) {
        const int c = t + i*256;
        o[c] = (v[i] - mu) * inv * gamma[c] + beta[c];
    }
}

// ============================================================================
// Launch
// ============================================================================
extern "C" void kernel_launch(void* const* d_in, const int* in_sizes, int n_in,
                              void* d_out, int out_size)
{
    const float* q     = (const float*)d_in[0];
    const float* k     = (const float*)d_in[1];
    const float* v     = (const float*)d_in[2];
    const float* Wq    = (const float*)d_in[3];
    const float* bq    = (const float*)d_in[4];
    const float* Wfc   = (const float*)d_in[5];
    const float* bfc   = (const float*)d_in[6];
    const float* gamma = (const float*)d_in[7];
    const float* beta  = (const float*)d_in[8];

    float* out = (float*)d_out;
    float* attn_region = ((size_t)out_size >= XE + AE) ? (out + XE) : nullptr;

    float *qh, *kh, *vh, *ao, *xb, *wtq, *wtfc;
    cudaGetSymbolAddress((void**)&qh,   g_qh);
    cudaGetSymbolAddress((void**)&kh,   g_kh);
    cudaGetSymbolAddress((void**)&vh,   g_vh);
    cudaGetSymbolAddress((void**)&ao,   g_ao);
    cudaGetSymbolAddress((void**)&xb,   g_x);
    cudaGetSymbolAddress((void**)&wtq,  g_wt_q);
    cudaGetSymbolAddress((void**)&wtfc, g_wt_fc);

    // Transpose weights to [N,K] K-major
    const dim3 gT(32, 32);
    transpose1024<<<gT, dim3(32, 8)>>>(Wq,  wtq);
    transpose1024<<<gT, dim3(32, 8)>>>(Wfc, wtfc);

    // Projections (tf32 mma). q gets the 1/sqrt(dk) scale folded in.
    const dim3 gG(Dc/128, (Bc*Sc)/128);        // (8, 64)
    gemm_mma<<<gG, 256>>>(q, wtq, bq, nullptr, qh, 1, SCALEc);
    gemm_mma<<<gG, 256>>>(k, wtq, bq, nullptr, kh, 1, 1.f);
    gemm_mma<<<gG, 256>>>(v, wtq, bq, nullptr, vh, 1, 1.f);

    const dim3 gScores(Sc/128, Sc/128, BHc);   // (16, 16, 64)
    scores_mma<<<gScores, 256>>>(qh, kh, attn_region);

    softmax_k<<<BHc * Sc, 256>>>(attn_region);

    const dim3 gAV(Sc/128, BHc);               // (16, 64)
    av_mma<<<gAV, 256>>>(attn_region, vh, ao);

    // FC + residual (tf32 mma), then LayerNorm
    gemm_mma<<<gG, 256>>>(ao, wtfc, bfc, q, xb, 0, 1.f);

    ln_k<<<Bc*Sc, 256>>>(xb, gamma, beta, out);
}